// round 11
// baseline (speedup 1.0000x reference)
#include <cuda_runtime.h>
#include <cstdint>
#include <cstddef>

#define C32 32
#define D8  8
#define TPB_TILES 8   // block = 4 warps x 32 rows x 8 iters = 1024 rows

typedef unsigned long long ull;

// ---- precomputed folded parameters (device scratch; no allocation) ----
__device__ __align__(16) float g_M1T[D8 * C32];   // folded layer-1 matrix
__device__ __align__(16) float g_c1[C32];         // folded layer-1 bias
__device__ __align__(16) float g_tbl[C32 * 4];    // per-col float4: (c2p, colsum, g2, be2)
// Pre-split layer-2 B fragments: [kt*4+nt][lane] -> (b0,b1) hi / lo tf32 words
__device__ __align__(16) uint2 g_B2h[16 * 32];
__device__ __align__(16) uint2 g_B2l[16 * 32];

// ---- constant mirrors for the FFMA layer-1 (broadcast; LDC port) ----
__constant__ __align__(16) float cM1T[D8 * C32];
__constant__ __align__(16) float cc1[C32];

// ---- packed f32x2 helpers ----
__device__ __forceinline__ ull pk2(float lo, float hi) {
    ull r;
    asm("mov.b64 %0, {%1, %2};" : "=l"(r) : "f"(lo), "f"(hi));
    return r;
}
__device__ __forceinline__ void upk2(ull v, float& lo, float& hi) {
    asm("mov.b64 {%0, %1}, %2;" : "=f"(lo), "=f"(hi) : "l"(v));
}
__device__ __forceinline__ void fma2(ull& d, ull a, ull b) {
    asm("fma.rn.f32x2 %0, %1, %2, %0;" : "+l"(d) : "l"(a), "l"(b));
}
__device__ __forceinline__ void add2(ull& d, ull a) {
    asm("add.rn.f32x2 %0, %0, %1;" : "+l"(d) : "l"(a));
}

// ---- tf32 helpers ----
__device__ __forceinline__ void split_tf32(float x, uint32_t& hi, uint32_t& lo) {
    asm("cvt.rna.tf32.f32 %0, %1;" : "=r"(hi) : "f"(x));
    float r = x - __uint_as_float(hi);
    asm("cvt.rna.tf32.f32 %0, %1;" : "=r"(lo) : "f"(r));
}

// D(16x8,f32) += A(16x8,tf32,row) * B(8x8,tf32,col)
__device__ __forceinline__ void mma8(float* d, const uint32_t* a, const uint32_t* b) {
    asm volatile(
        "mma.sync.aligned.m16n8k8.row.col.f32.tf32.tf32.f32 "
        "{%0,%1,%2,%3}, {%4,%5,%6,%7}, {%8,%9}, {%0,%1,%2,%3};"
        : "+f"(d[0]), "+f"(d[1]), "+f"(d[2]), "+f"(d[3])
        : "r"(a[0]), "r"(a[1]), "r"(a[2]), "r"(a[3]), "r"(b[0]), "r"(b[1]));
}

// ============================================================================
// Precompute: folded matrices (verified through R10) + pre-split B fragments.
// ============================================================================
__global__ void gnn_precompute_kernel(const float* __restrict__ adjacency,
                                      const float* __restrict__ W1,
                                      const float* __restrict__ b1,
                                      const float* __restrict__ W2,
                                      const float* __restrict__ b2,
                                      const float* __restrict__ g1,
                                      const float* __restrict__ be1,
                                      const float* __restrict__ g2,
                                      const float* __restrict__ be2) {
    __shared__ float A[C32][C32];
    __shared__ float dis[C32];
    __shared__ float Ms[C32][C32];   // M2T[k][i]
    __shared__ float Gs[C32][C32];   // G2T[k][i]
    int t = threadIdx.x;
    int i = t >> 5;
    int j = t & 31;

    float a = adjacency[i * C32 + j] + (i == j ? 1.0f : 0.0f);
    A[i][j] = a;
    __syncthreads();

    if (j == 0) {
        float s = 0.0f;
        #pragma unroll
        for (int k = 0; k < C32; k++) s += A[i][k];
        dis[i] = rsqrtf(s + 1e-6f);
    }
    __syncthreads();
    float na = dis[i] * A[i][j] * dis[j];
    __syncthreads();
    A[i][j] = na;
    __syncthreads();

    {
        int k = j;
        float s = 0.0f;
        #pragma unroll
        for (int jj = 0; jj < C32; jj++) s += A[i][jj] * W2[jj * C32 + k];
        Ms[k][i] = s;
        Gs[k][i] = g1[k] * s;
    }
    if (t < C32 * D8) {
        int ii = t >> 3;
        int d  = t & 7;
        float s = 0.0f;
        #pragma unroll
        for (int jj = 0; jj < C32; jj++) s += A[ii][jj] * W1[jj * D8 + d];
        g_M1T[d * C32 + ii] = s;
    }
    if (t < C32) {
        float s1 = 0.0f;
        #pragma unroll
        for (int jj = 0; jj < C32; jj++) s1 += A[t][jj] * b1[jj];
        g_c1[t] = s1;
    }
    __syncthreads();

    if (t < C32) {
        float cs = 0.0f, cp = 0.0f, c2 = 0.0f;
        #pragma unroll
        for (int k = 0; k < C32; k++) {
            cs += Gs[k][t];
            cp += be1[k] * Ms[k][t];
            c2 += A[t][k] * b2[k];
        }
        ((float4*)g_tbl)[t] = make_float4(c2 + cp, cs, g2[t], be2[t]);
    }

    // Pre-split B fragments for the m16n8k8 col-major layout:
    // lane(g=ln>>2, tt=ln&3) of (kt,nt) holds b0=G2T[kt*8+tt][nt*8+g],
    // b1=G2T[kt*8+tt+4][nt*8+g]; store tf32 hi/lo pairs.
    if (t < 512) {
        int ktnt = t >> 5, ln = t & 31;
        int gg = ln >> 2, tt = ln & 3;
        int kt = ktnt >> 2, nt = ktnt & 3;
        float b0 = Gs[kt * 8 + tt][nt * 8 + gg];
        float b1v = Gs[kt * 8 + tt + 4][nt * 8 + gg];
        uint32_t h0, l0, h1, l1;
        split_tf32(b0, h0, l0);
        split_tf32(b1v, h1, l1);
        g_B2h[t] = make_uint2(h0, h1);
        g_B2l[t] = make_uint2(l0, l1);
    }
}

// ============================================================================
// Main kernel: 128 threads = 4 warps; warp owns 32 rows per tile.
//  Layer 1: FFMA2 per-lane-row from constant port + thread-local LN1.
//  u staged to smem ALREADY SPLIT into tf32 (hi,lo) pairs -> MMA loop is pure
//  LDS.64 + MMA (no cvt on the feed path). B fragments pre-split (precompute)
//  and served from smem -> ~64 registers freed -> 4 blocks/SM.
// ============================================================================
__global__ __launch_bounds__(128, 4) void gnn_main_kernel(
    const float* __restrict__ x,
    float* __restrict__ out, int nrows) {

    __shared__ __align__(16) float4 sTBL[C32];
    __shared__ __align__(16) uint2  sBh[16 * 32];
    __shared__ __align__(16) uint2  sBl[16 * 32];
    __shared__ __align__(16) uint2  u_s[4][32 * 36];   // per-warp split-u tile, pitch 36 uint2

    int tid = threadIdx.x;
    if (tid < 32) sTBL[tid] = ((const float4*)g_tbl)[tid];
    // B fragment tables: 512 uint2 each = 256 uint4 each
    ((uint4*)sBh)[tid]       = ((const uint4*)g_B2h)[tid];
    ((uint4*)sBh)[tid + 128] = ((const uint4*)g_B2h)[tid + 128];
    ((uint4*)sBl)[tid]       = ((const uint4*)g_B2l)[tid];
    ((uint4*)sBl)[tid + 128] = ((const uint4*)g_B2l)[tid + 128];
    __syncthreads();

    int w = tid >> 5, lane = tid & 31;
    int g = lane >> 2, t = lane & 3;
    uint2* myu = u_s[w];

    // ---- prefetch x for tile 0 ----
    float4 xa0 = make_float4(0, 0, 0, 0), xa1 = xa0;
    {
        int row = blockIdx.x * TPB_TILES * 128 + w * 32 + lane;
        if (row < nrows) {
            const float4* xv = reinterpret_cast<const float4*>(x + (size_t)row * D8);
            xa0 = xv[0];
            xa1 = xv[1];
        }
    }

    for (int tile = 0; tile < TPB_TILES; tile++) {
        int rowbase = (blockIdx.x * TPB_TILES + tile) * 128 + w * 32;

        // ---- prefetch next tile's x ----
        float4 xn0 = make_float4(0, 0, 0, 0), xn1 = xn0;
        if (tile + 1 < TPB_TILES) {
            int nr = rowbase + 128 + lane;
            if (nr < nrows) {
                const float4* xv = reinterpret_cast<const float4*>(x + (size_t)nr * D8);
                xn0 = xv[0];
                xn1 = xv[1];
            }
        }

        // ==== layer 1 (FFMA2, per-lane row, matrix+bias from constant) ====
        float xr[8] = {xa0.x, xa0.y, xa0.z, xa0.w, xa1.x, xa1.y, xa1.z, xa1.w};
        ull h[16];
        {
            const ulonglong2* cv = reinterpret_cast<const ulonglong2*>(cc1);
            #pragma unroll
            for (int q = 0; q < 8; q++) {
                ulonglong2 c = cv[q];
                h[2 * q] = c.x;
                h[2 * q + 1] = c.y;
            }
        }
        #pragma unroll
        for (int d = 0; d < D8; d++) {
            ull ad = pk2(xr[d], xr[d]);
            const ulonglong2* mr = reinterpret_cast<const ulonglong2*>(cM1T + d * C32);
            #pragma unroll
            for (int q = 0; q < 8; q++) {
                ulonglong2 mm = mr[q];
                fma2(h[2 * q],     ad, mm.x);
                fma2(h[2 * q + 1], ad, mm.y);
            }
        }

        // ==== relu + thread-local LN1 stats ====
        ull sp = 0ULL, ssp = 0ULL;
        #pragma unroll
        for (int i = 0; i < 16; i++) {
            float lo, hi;
            upk2(h[i], lo, hi);
            lo = fmaxf(lo, 0.0f);
            hi = fmaxf(hi, 0.0f);
            h[i] = pk2(lo, hi);
            add2(sp, h[i]);
            fma2(ssp, h[i], h[i]);
        }
        float s0, s1, q0, q1;
        upk2(sp, s0, s1); upk2(ssp, q0, q1);
        float m1 = (s0 + s1) * (1.0f / 32.0f);
        float v1 = (q0 + q1) * (1.0f / 32.0f) - m1 * m1;
        float r1 = rsqrtf(v1 + 1e-5f);

        // ==== stage u row as split tf32 (hi,lo) pairs; burst of cvts here,
        //      off the MMA feed path ====
        uint2* urow = &myu[lane * 36];
        #pragma unroll
        for (int i = 0; i < 16; i++) {
            float lo, hi;
            upk2(h[i], lo, hi);      // values v0=col 2i (lo), v1=col 2i+1 (hi)
            uint32_t h0, l0, h1, l1;
            split_tf32(lo, h0, l0);
            split_tf32(hi, h1, l1);
            *reinterpret_cast<uint4*>(urow + 2 * i) = make_uint4(h0, l0, h1, l1);
        }
        __syncwarp();

        // ---- cross m1/r1 from lane-layout to frag-layout (rows g+8s) ----
        float m1v[4], r1v[4];
        #pragma unroll
        for (int s = 0; s < 4; s++) {
            m1v[s] = __shfl_sync(0xffffffffu, m1, g + 8 * s);
            r1v[s] = __shfl_sync(0xffffffffu, r1, g + 8 * s);
        }

        // ==== layer 2: D2 = u @ G2T, pure LDS.64 + MMA, 8 independent chains ====
        float D2[2][4][4];
        #pragma unroll
        for (int mt = 0; mt < 2; mt++)
            #pragma unroll
            for (int nt = 0; nt < 4; nt++)
                #pragma unroll
                for (int q = 0; q < 4; q++) D2[mt][nt][q] = 0.0f;

        #pragma unroll
        for (int kt = 0; kt < 4; kt++) {
            int c = kt * 8 + t;
            uint32_t ah[2][4], al[2][4];
            #pragma unroll
            for (int mt = 0; mt < 2; mt++) {
                int r0 = g + 16 * mt, r1r = r0 + 8;
                uint2 a0 = myu[r0  * 36 + c];
                uint2 a1 = myu[r1r * 36 + c];
                uint2 a2 = myu[r0  * 36 + c + 4];
                uint2 a3 = myu[r1r * 36 + c + 4];
                ah[mt][0] = a0.x; al[mt][0] = a0.y;
                ah[mt][1] = a1.x; al[mt][1] = a1.y;
                ah[mt][2] = a2.x; al[mt][2] = a2.y;
                ah[mt][3] = a3.x; al[mt][3] = a3.y;
            }
            uint32_t bh[4][2], bl[4][2];
            #pragma unroll
            for (int nt = 0; nt < 4; nt++) {
                uint2 vh = sBh[(kt * 4 + nt) * 32 + lane];
                uint2 vl = sBl[(kt * 4 + nt) * 32 + lane];
                bh[nt][0] = vh.x; bh[nt][1] = vh.y;
                bl[nt][0] = vl.x; bl[nt][1] = vl.y;
            }
            // three product sweeps -> RAW distance 8 between same-acc MMAs
            #pragma unroll
            for (int mt = 0; mt < 2; mt++)
                #pragma unroll
                for (int nt = 0; nt < 4; nt++) mma8(D2[mt][nt], ah[mt], bh[nt]);
            #pragma unroll
            for (int mt = 0; mt < 2; mt++)
                #pragma unroll
                for (int nt = 0; nt < 4; nt++) mma8(D2[mt][nt], ah[mt], bl[nt]);
            #pragma unroll
            for (int mt = 0; mt < 2; mt++)
                #pragma unroll
                for (int nt = 0; nt < 4; nt++) mma8(D2[mt][nt], al[mt], bh[nt]);
        }
        __syncwarp();   // u_s reads done before next tile's staging

        // ==== fold LN1 + relu, IN PLACE in D2; LN2 stats ====
        float sum2[4] = {0, 0, 0, 0}, ssq2[4] = {0, 0, 0, 0};
        #pragma unroll
        for (int nt = 0; nt < 4; nt++) {
            float4 tb0 = sTBL[nt * 8 + 2 * t];
            float4 tb1 = sTBL[nt * 8 + 2 * t + 1];
            #pragma unroll
            for (int s = 0; s < 4; s++) {
                int mt = s >> 1, hh = s & 1;
                float v0 = fmaf(r1v[s], fmaf(-m1v[s], tb0.y, D2[mt][nt][2 * hh + 0]), tb0.x);
                float vB = fmaf(r1v[s], fmaf(-m1v[s], tb1.y, D2[mt][nt][2 * hh + 1]), tb1.x);
                v0 = fmaxf(v0, 0.0f);
                vB = fmaxf(vB, 0.0f);
                D2[mt][nt][2 * hh + 0] = v0;
                D2[mt][nt][2 * hh + 1] = vB;
                sum2[s] += v0 + vB;
                ssq2[s] = fmaf(v0, v0, fmaf(vB, vB, ssq2[s]));
            }
        }
        float m2v[4], r2v[4];
        #pragma unroll
        for (int s = 0; s < 4; s++) {
            float sum = sum2[s], ssq = ssq2[s];
            sum += __shfl_xor_sync(0xffffffffu, sum, 1);
            ssq += __shfl_xor_sync(0xffffffffu, ssq, 1);
            sum += __shfl_xor_sync(0xffffffffu, sum, 2);
            ssq += __shfl_xor_sync(0xffffffffu, ssq, 2);
            float mm = sum * (1.0f / 32.0f);
            float vv = fmaf(ssq, 1.0f / 32.0f, -mm * mm);
            m2v[s] = mm;
            r2v[s] = rsqrtf(vv + 1e-5f);
        }

        // ==== epilogue: out = (h2 - m2)*r2*g2 + be2, direct STG.64 ====
        #pragma unroll
        for (int s = 0; s < 4; s++) {
            int grow = rowbase + g + 8 * s;
            if (grow < nrows) {
                int mt = s >> 1, hh = s & 1;
                float r2 = r2v[s], m2 = m2v[s];
                float* op = out + (size_t)grow * C32;
                #pragma unroll
                for (int nt = 0; nt < 4; nt++) {
                    float4 tb0 = sTBL[nt * 8 + 2 * t];
                    float4 tb1 = sTBL[nt * 8 + 2 * t + 1];
                    float w0 = r2 * tb0.z, w1 = r2 * tb1.z;
                    float o0 = fmaf(D2[mt][nt][2 * hh + 0], w0, fmaf(-m2, w0, tb0.w));
                    float o1 = fmaf(D2[mt][nt][2 * hh + 1], w1, fmaf(-m2, w1, tb1.w));
                    *(float2*)&op[nt * 8 + 2 * t] = make_float2(o0, o1);
                }
            }
        }
        __syncwarp();

        xa0 = xn0;
        xa1 = xn1;
    }
}

extern "C" void kernel_launch(void* const* d_in, const int* in_sizes, int n_in,
                              void* d_out, int out_size) {
    const float* x         = (const float*)d_in[0];
    const float* adjacency = (const float*)d_in[1];
    const float* W1        = (const float*)d_in[2];
    const float* b1        = (const float*)d_in[3];
    const float* W2        = (const float*)d_in[4];
    const float* b2        = (const float*)d_in[5];
    const float* g1        = (const float*)d_in[6];
    const float* be1       = (const float*)d_in[7];
    const float* g2        = (const float*)d_in[8];
    const float* be2       = (const float*)d_in[9];
    float* out = (float*)d_out;

    int nrows = in_sizes[0] / D8;

    gnn_precompute_kernel<<<1, 1024>>>(adjacency, W1, b1, W2, b2, g1, be1, g2, be2);

    // constant-port mirrors for layer 1 (D2D async copies; graph-capturable)
    void *pM1T, *pc1;
    cudaGetSymbolAddress(&pM1T, g_M1T);
    cudaGetSymbolAddress(&pc1,  g_c1);
    cudaMemcpyToSymbolAsync(cM1T, pM1T, D8 * C32 * sizeof(float), 0, cudaMemcpyDeviceToDevice, 0);
    cudaMemcpyToSymbolAsync(cc1,  pc1,  C32 * sizeof(float),      0, cudaMemcpyDeviceToDevice, 0);

    int rows_per_block = TPB_TILES * 128;
    int blocks = (nrows + rows_per_block - 1) / rows_per_block;
    gnn_main_kernel<<<blocks, 128>>>(x, out, nrows);
}

// round 13
// speedup vs baseline: 1.2902x; 1.2902x over previous
#include <cuda_runtime.h>
#include <cuda_bf16.h>

#define C32 32
#define D8  8

typedef unsigned long long ull;

// ---- packed parameter block layout (floats) ----
//  [0,256)    M1T[d][i]
//  [256,288)  c1
//  [288,800)  G2A  (G2T cols 0..15, k-major: [k][0..15])
//  [800,832)  c2p
//  [832,864)  colsum
//  [864,896)  g2
//  [896,928)  be2
#define OFF_M1T 0
#define OFF_C1  256
#define OFF_G2A 288
#define OFF_C2P 800
#define OFF_COL 832
#define OFF_G2  864
#define OFF_BE2 896
#define PACK_N  928

__device__ __align__(16) float g_PACK[PACK_N];     // written by precompute
__device__ __align__(16) float g_G2B[C32 * 16];    // G2T cols 16..31 (smem path)

__constant__ __align__(16) float cPACK[PACK_N];    // single-memcpy constant mirror

// ---- packed f32x2 helpers (Blackwell FFMA2/FADD2/FMUL2, PTX-only) ----
__device__ __forceinline__ ull pk2(float lo, float hi) {
    ull r;
    asm("mov.b64 %0, {%1, %2};" : "=l"(r) : "f"(lo), "f"(hi));
    return r;
}
__device__ __forceinline__ void upk2(ull v, float& lo, float& hi) {
    asm("mov.b64 {%0, %1}, %2;" : "=f"(lo), "=f"(hi) : "l"(v));
}
__device__ __forceinline__ void fma2(ull& d, ull a, ull b) {
    asm("fma.rn.f32x2 %0, %1, %2, %0;" : "+l"(d) : "l"(a), "l"(b));
}
__device__ __forceinline__ void add2(ull& d, ull a) {
    asm("add.rn.f32x2 %0, %0, %1;" : "+l"(d) : "l"(a));
}
__device__ __forceinline__ void mul2(ull& d, ull a, ull b) {
    asm("mul.rn.f32x2 %0, %1, %2;" : "=l"(d) : "l"(a), "l"(b));
}

// ============================================================================
// Precompute: normalized adjacency folded into both layers, LN1 affine folded
// into layer 2 (derivation verified since R4). Writes the packed block.
// ============================================================================
__global__ void gnn_precompute_kernel(const float* __restrict__ adjacency,
                                      const float* __restrict__ W1,
                                      const float* __restrict__ b1,
                                      const float* __restrict__ W2,
                                      const float* __restrict__ b2,
                                      const float* __restrict__ g1,
                                      const float* __restrict__ be1,
                                      const float* __restrict__ g2,
                                      const float* __restrict__ be2) {
    __shared__ float A[C32][C32];
    __shared__ float dis[C32];
    __shared__ float Ms[C32][C32];   // M2T[k][i]
    __shared__ float Gs[C32][C32];   // G2T[k][i]
    int t = threadIdx.x;
    int i = t >> 5;
    int j = t & 31;

    float a = adjacency[i * C32 + j] + (i == j ? 1.0f : 0.0f);
    A[i][j] = a;
    __syncthreads();

    if (j == 0) {
        float s = 0.0f;
        #pragma unroll
        for (int k = 0; k < C32; k++) s += A[i][k];
        dis[i] = rsqrtf(s + 1e-6f);
    }
    __syncthreads();
    float na = dis[i] * A[i][j] * dis[j];
    __syncthreads();
    A[i][j] = na;   // A is now norm_adj
    __syncthreads();

    // M2T[k][i] for k = j
    {
        int k = j;
        float s = 0.0f;
        #pragma unroll
        for (int jj = 0; jj < C32; jj++) s += A[i][jj] * W2[jj * C32 + k];
        Ms[k][i] = s;
        float g = g1[k] * s;
        Gs[k][i] = g;
        if (i < 16) g_PACK[OFF_G2A + k * 16 + i] = g;
        else        g_G2B[k * 16 + (i - 16)] = g;
    }
    // M1T[d][i]
    if (t < C32 * D8) {
        int ii = t >> 3;
        int d  = t & 7;
        float s = 0.0f;
        #pragma unroll
        for (int jj = 0; jj < C32; jj++) s += A[ii][jj] * W1[jj * D8 + d];
        g_PACK[OFF_M1T + d * C32 + ii] = s;
    }
    // c1
    if (t < C32) {
        float s1 = 0.0f;
        #pragma unroll
        for (int jj = 0; jj < C32; jj++) s1 += A[t][jj] * b1[jj];
        g_PACK[OFF_C1 + t] = s1;
    }
    __syncthreads();

    // colsum, c2p, g2, be2
    if (t < C32) {
        float cs = 0.0f, cp = 0.0f, c2 = 0.0f;
        #pragma unroll
        for (int k = 0; k < C32; k++) {
            cs += Gs[k][t];
            cp += be1[k] * Ms[k][t];
            c2 += A[t][k] * b2[k];
        }
        g_PACK[OFF_COL + t] = cs;
        g_PACK[OFF_C2P + t] = c2 + cp;
        g_PACK[OFF_G2 + t]  = g2[t];
        g_PACK[OFF_BE2 + t] = be2[t];
    }
}

// ---- per-row helpers (split partial sums -> half-depth dependency chains) ----
__device__ __forceinline__ void relu_stats(ull* v, float& m, float& r) {
    ull sp0 = 0ULL, sp1 = 0ULL, ssp0 = 0ULL, ssp1 = 0ULL;
    #pragma unroll
    for (int i = 0; i < 16; i += 2) {
        float lo, hi;
        upk2(v[i], lo, hi);
        lo = fmaxf(lo, 0.0f);
        hi = fmaxf(hi, 0.0f);
        v[i] = pk2(lo, hi);
        add2(sp0, v[i]);
        fma2(ssp0, v[i], v[i]);
        upk2(v[i + 1], lo, hi);
        lo = fmaxf(lo, 0.0f);
        hi = fmaxf(hi, 0.0f);
        v[i + 1] = pk2(lo, hi);
        add2(sp1, v[i + 1]);
        fma2(ssp1, v[i + 1], v[i + 1]);
    }
    add2(sp0, sp1);
    add2(ssp0, ssp1);
    float s0, s1, q0, q1;
    upk2(sp0, s0, s1); upk2(ssp0, q0, q1);
    m = (s0 + s1) * (1.0f / 32.0f);
    float vv = (q0 + q1) * (1.0f / 32.0f) - m * m;
    r = rsqrtf(vv + 1e-5f);
}

__device__ __forceinline__ void fold_ln1(ull* acc, float m, float r) {
    ull nm = pk2(-m, -m);
    ull rp = pk2(r, r);
    const ulonglong2* cv = reinterpret_cast<const ulonglong2*>(cPACK + OFF_C2P);
    const ulonglong2* kv = reinterpret_cast<const ulonglong2*>(cPACK + OFF_COL);
    #pragma unroll
    for (int q = 0; q < 8; q++) {
        ulonglong2 cc = cv[q];
        ulonglong2 kk = kv[q];
        fma2(acc[2*q],   nm, kk.x);
        fma2(acc[2*q+1], nm, kk.y);
        ull t0 = cc.x; fma2(t0, rp, acc[2*q]);   acc[2*q]   = t0;
        ull t1 = cc.y; fma2(t1, rp, acc[2*q+1]); acc[2*q+1] = t1;
    }
}

__device__ __forceinline__ void epilogue_stage(ull* acc, float m2, float r2,
                                               float* buf) {
    ull r2p  = pk2(r2, r2);
    ull mr2p = pk2(-m2 * r2, -m2 * r2);
    const ulonglong2* gv = reinterpret_cast<const ulonglong2*>(cPACK + OFF_G2);
    const ulonglong2* bv = reinterpret_cast<const ulonglong2*>(cPACK + OFF_BE2);
    #pragma unroll
    for (int q = 0; q < 8; q++) {
        ulonglong2 gg = gv[q];
        ulonglong2 bb = bv[q];
        ull w0, w1;
        mul2(w0, gg.x, r2p);
        mul2(w1, gg.y, r2p);
        ull o0 = bb.x; fma2(o0, mr2p, gg.x); fma2(o0, acc[2*q],   w0);
        ull o1 = bb.y; fma2(o1, mr2p, gg.y); fma2(o1, acc[2*q+1], w1);
        float a0, a1, a2, a3;
        upk2(o0, a0, a1);
        upk2(o1, a2, a3);
        *reinterpret_cast<float4*>(buf + q * 4) = make_float4(a0, a1, a2, a3);
    }
}

// ============================================================================
// Main fused kernel (R7 architecture, measured-best): 128 threads/block,
// 2 rows/thread. Layer-2 matrix split: cols 0..15 via constant port (LDC),
// cols 16..31 via smem crossbar (LDS). Layer-1 matrix, biases, LN params via
// constant port. Coalesced stores via padded warp-local smem transpose.
// ============================================================================
__global__ __launch_bounds__(128) void gnn_main_kernel(
    const float* __restrict__ x,
    float* __restrict__ out, int nrows) {

    __shared__ __align__(16) float sG2B[C32 * 16];
    __shared__ __align__(16) float stg[4][32 * 36];   // per-warp staging, pitch 36

    int t = threadIdx.x;
    ((float4*)sG2B)[t] = ((const float4*)g_G2B)[t];   // 512 floats = 128 float4
    __syncthreads();

    int w = t >> 5, l = t & 31;
    int rowA = blockIdx.x * 256 + t;
    int rowB = rowA + 128;
    bool actA = (rowA < nrows);
    bool actB = (rowB < nrows);

    ull ha[16], hb[16];   // layer1 accum / relu'd u
    ull aa[16], ab[16];   // layer2 accum

    // ---- load x rows ----
    float xra[8] = {0,0,0,0,0,0,0,0}, xrb[8] = {0,0,0,0,0,0,0,0};
    if (actA) {
        const float4* xv = reinterpret_cast<const float4*>(x + (size_t)rowA * D8);
        float4 a0 = xv[0], a1 = xv[1];
        xra[0]=a0.x; xra[1]=a0.y; xra[2]=a0.z; xra[3]=a0.w;
        xra[4]=a1.x; xra[5]=a1.y; xra[6]=a1.z; xra[7]=a1.w;
    }
    if (actB) {
        const float4* xv = reinterpret_cast<const float4*>(x + (size_t)rowB * D8);
        float4 b0 = xv[0], b1 = xv[1];
        xrb[0]=b0.x; xrb[1]=b0.y; xrb[2]=b0.z; xrb[3]=b0.w;
        xrb[4]=b1.x; xrb[5]=b1.y; xrb[6]=b1.z; xrb[7]=b1.w;
    }

    // ---- layer 1 (matrix + bias from constant port) ----
    {
        const ulonglong2* cv = reinterpret_cast<const ulonglong2*>(cPACK + OFF_C1);
        #pragma unroll
        for (int q = 0; q < 8; q++) {
            ulonglong2 c = cv[q];
            ha[2*q] = c.x; ha[2*q+1] = c.y;
            hb[2*q] = c.x; hb[2*q+1] = c.y;
        }
    }
    #pragma unroll
    for (int d = 0; d < D8; d++) {
        ull adA = pk2(xra[d], xra[d]);
        ull adB = pk2(xrb[d], xrb[d]);
        const ulonglong2* mr = reinterpret_cast<const ulonglong2*>(cPACK + OFF_M1T + d * C32);
        #pragma unroll
        for (int q = 0; q < 8; q++) {
            ulonglong2 mm = mr[q];
            fma2(ha[2*q],   adA, mm.x);
            fma2(ha[2*q+1], adA, mm.y);
            fma2(hb[2*q],   adB, mm.x);
            fma2(hb[2*q+1], adB, mm.y);
        }
    }

    // ---- relu + LN1 stats ----
    float mA, rA, mB, rB;
    relu_stats(ha, mA, rA);
    relu_stats(hb, mB, rB);

    // ---- layer 2: cols 0..15 from constant (acc[0..7]),
    //               cols 16..31 from smem (acc[8..15]) ----
    #pragma unroll
    for (int i = 0; i < 16; i++) { aa[i] = 0ULL; ab[i] = 0ULL; }
    #pragma unroll
    for (int p = 0; p < 16; p++) {
        float u0A, u1A, u0B, u1B;
        upk2(ha[p], u0A, u1A);
        upk2(hb[p], u0B, u1B);
        ull a0A = pk2(u0A, u0A), a1A = pk2(u1A, u1A);
        ull a0B = pk2(u0B, u0B), a1B = pk2(u1B, u1B);
        const ulonglong2* ca0 = reinterpret_cast<const ulonglong2*>(cPACK + OFF_G2A + (2*p)   * 16);
        const ulonglong2* ca1 = reinterpret_cast<const ulonglong2*>(cPACK + OFF_G2A + (2*p+1) * 16);
        const ulonglong2* sb0 = reinterpret_cast<const ulonglong2*>(sG2B + (2*p)   * 16);
        const ulonglong2* sb1 = reinterpret_cast<const ulonglong2*>(sG2B + (2*p+1) * 16);
        #pragma unroll
        for (int q = 0; q < 4; q++) {
            ulonglong2 m0 = ca0[q];
            fma2(aa[2*q],   a0A, m0.x);
            fma2(aa[2*q+1], a0A, m0.y);
            fma2(ab[2*q],   a0B, m0.x);
            fma2(ab[2*q+1], a0B, m0.y);
            ulonglong2 s0 = sb0[q];
            fma2(aa[8+2*q],   a0A, s0.x);
            fma2(aa[8+2*q+1], a0A, s0.y);
            fma2(ab[8+2*q],   a0B, s0.x);
            fma2(ab[8+2*q+1], a0B, s0.y);
        }
        #pragma unroll
        for (int q = 0; q < 4; q++) {
            ulonglong2 m1 = ca1[q];
            fma2(aa[2*q],   a1A, m1.x);
            fma2(aa[2*q+1], a1A, m1.y);
            fma2(ab[2*q],   a1B, m1.x);
            fma2(ab[2*q+1], a1B, m1.y);
            ulonglong2 s1 = sb1[q];
            fma2(aa[8+2*q],   a1A, s1.x);
            fma2(aa[8+2*q+1], a1A, s1.y);
            fma2(ab[8+2*q],   a1B, s1.x);
            fma2(ab[8+2*q+1], a1B, s1.y);
        }
    }

    // ---- fold LN1, relu + LN2 ----
    fold_ln1(aa, mA, rA);
    fold_ln1(ab, mB, rB);

    float m2A, r2A, m2B, r2B;
    relu_stats(aa, m2A, r2A);
    relu_stats(ab, m2B, r2B);

    float* buf = &stg[w][l * 36];
    const float* wb = &stg[w][0];

    // --- tile A: epilogue + coalesced store via padded smem transpose ---
    if (actA) epilogue_stage(aa, m2A, r2A, buf);
    __syncwarp();
    {
        int rowbase = blockIdx.x * 256 + w * 32;
        float4* odst = reinterpret_cast<float4*>(out + (size_t)rowbase * C32);
        #pragma unroll
        for (int q = 0; q < 8; q++) {
            int idx4 = l + q * 32;
            int rr = idx4 >> 3;
            int c4 = idx4 & 7;
            if (rowbase + rr < nrows) {
                float4 v = *reinterpret_cast<const float4*>(wb + rr * 36 + c4 * 4);
                odst[idx4] = v;
            }
        }
    }
    __syncwarp();

    // --- tile B (reuse buffer) ---
    if (actB) epilogue_stage(ab, m2B, r2B, buf);
    __syncwarp();
    {
        int rowbase = blockIdx.x * 256 + 128 + w * 32;
        float4* odst = reinterpret_cast<float4*>(out + (size_t)rowbase * C32);
        #pragma unroll
        for (int q = 0; q < 8; q++) {
            int idx4 = l + q * 32;
            int rr = idx4 >> 3;
            int c4 = idx4 & 7;
            if (rowbase + rr < nrows) {
                float4 v = *reinterpret_cast<const float4*>(wb + rr * 36 + c4 * 4);
                odst[idx4] = v;
            }
        }
    }
}

extern "C" void kernel_launch(void* const* d_in, const int* in_sizes, int n_in,
                              void* d_out, int out_size) {
    const float* x         = (const float*)d_in[0];
    const float* adjacency = (const float*)d_in[1];
    const float* W1        = (const float*)d_in[2];
    const float* b1        = (const float*)d_in[3];
    const float* W2        = (const float*)d_in[4];
    const float* b2        = (const float*)d_in[5];
    const float* g1        = (const float*)d_in[6];
    const float* be1       = (const float*)d_in[7];
    const float* g2        = (const float*)d_in[8];
    const float* be2       = (const float*)d_in[9];
    float* out = (float*)d_out;

    int nrows = in_sizes[0] / D8;  // B*TF*C rows of D=8

    gnn_precompute_kernel<<<1, 1024>>>(adjacency, W1, b1, W2, b2, g1, be1, g2, be2);

    // ONE constant-memory copy for the whole packed parameter block
    // (D2D async memcpy; graph-capturable node).
    void* pPACK;
    cudaGetSymbolAddress(&pPACK, g_PACK);
    cudaMemcpyToSymbolAsync(cPACK, pPACK, PACK_N * sizeof(float), 0,
                            cudaMemcpyDeviceToDevice, 0);

    int blocks = (nrows + 255) / 256;   // 256 rows per block (2 per thread)
    gnn_main_kernel<<<blocks, 128>>>(x, out, nrows);
}